// round 14
// baseline (speedup 1.0000x reference)
#include <cuda_runtime.h>
#include <math.h>

#define MAXN   16384
#define HDIM   128
#define NSTEPS 64
#define THRS   5e-5f

// ---------------- device state ----------------
__device__ float g_start[MAXN], g_end[MAXN];
__device__ float g_next_s[MAXN], g_next_e[MAXN];
__device__ float g_curr_s[MAXN], g_curr_e[MAXN];
__device__ unsigned char g_uf_s[MAXN], g_uf_e[MAXN];
__device__ unsigned char g_workf[MAXN], g_secf[MAXN], g_convf[MAXN];
__device__ float g_zlow[MAXN], g_zhigh[MAXN], g_slow[MAXN], g_shigh[MAXN];
__device__ float g_zpred[MAXN], g_cand[MAXN];
__device__ int g_cnt[64];
__device__ int g_la[MAXN], g_lb[MAXN], g_lc[MAXN], g_ld[MAXN], g_lw[MAXN], g_ls[MAXN];

// jax.nn.softplus(x) = max(x,0) + log1p(exp(-|x|))  [libdevice expf/log1pf]
__device__ __forceinline__ float softplus_x(float x) {
    return __fadd_rn(fmaxf(x, 0.0f), log1pf(expf(-fabsf(x))));
}
// jnp.linspace(0,1,64)[i]
__device__ __forceinline__ float lint(int i) {
    return (i == 63) ? 1.0f : __fdiv_rn((float)i, 63.0f);
}
// pts_int = start + t*(end-start), uncontracted rn
__device__ __forceinline__ float ptsint(float s, float e, float t) {
    return __fadd_rn(s, __fmul_rn(t, __fsub_rn(e, s)));
}

// ---------------- templated eval kernel ----------------
// Per-point math bit-identical to the passing r7-r13 kernels
// (ascending-k fma, bias-after, gemv2T-8 layer 3).
// TMc = tile size (points per block). Mode 1 (dense march, 1 ray/tile,
// fused argmin reduce) requires TMc == 64.
// fuse: 0=plain write, 1=linestep epilogue, 2=secant-update epilogue.
template <int TMc>
__global__ void __launch_bounds__(256) eval_kernel(
    int mode, int fuse, int cidxA, int cidxB, int xA, int xB, int gridA,
    const float* __restrict__ rayo, const float* __restrict__ rayd,
    const float* __restrict__ W1, const float* __restrict__ b1,
    const float* __restrict__ W2, const float* __restrict__ b2,
    const float* __restrict__ W3, const float* __restrict__ b3,
    const int* __restrict__ listA, const int* __restrict__ listB,
    const float* __restrict__ tvalsA, const float* __restrict__ tvalsB,
    float* __restrict__ outA, float* __restrict__ outB,
    const int* __restrict__ obj)
{
    // shared layout (floats), computed from TMc
    constexpr int HHSZ   = (HDIM * TMc > TMc * 129) ? HDIM * TMc : TMc * 129;
    constexpr int OFF_PS  = HHSZ;
    constexpr int OFF_W1  = OFF_PS + 4 * TMc;
    constexpr int OFF_B1  = OFF_W1 + 3 * HDIM;
    constexpr int OFF_B2  = OFF_B1 + HDIM;
    constexpr int OFF_W3  = OFF_B2 + HDIM;
    constexpr int OFF_B3  = OFF_W3 + HDIM;
    constexpr int OFF_OIX = OFF_B3 + 4;
    constexpr int OFF_SV  = OFF_OIX + TMc;

    extern __shared__ float sbuf[];
    float* HsT = sbuf;                // pitch TMc during GEMM
    float* H3  = sbuf;                // pitch 129 after GEMM (aliased)
    float* Ps  = sbuf + OFF_PS;
    float* w1s = sbuf + OFF_W1;
    float* b1s = sbuf + OFF_B1;
    float* b2s = sbuf + OFF_B2;
    float* w3s = sbuf + OFF_W3;
    float* b3s = sbuf + OFF_B3;
    float* svs = sbuf + OFF_SV;
    int*   oix = (int*)(sbuf + OFF_OIX);

    const int tid = threadIdx.x;
    const int side = (blockIdx.x >= gridA) ? 1 : 0;
    const int lb   = side ? (blockIdx.x - gridA) : blockIdx.x;
    int rcnt = g_cnt[side ? cidxB : cidxA];
    int pcnt = (mode == 1) ? (rcnt << 6) : rcnt;
    if (lb * TMc >= pcnt) return;   // idle block

    const int*   list  = side ? listB  : listA;
    const float* tvals = side ? tvalsB : tvalsA;
    float*       outp  = side ? outB   : outA;

    for (int i = tid; i < 3 * HDIM; i += 256) w1s[i] = W1[i];
    if (tid < HDIM) { b1s[tid] = b1[tid]; b2s[tid] = b2[tid]; w3s[tid] = W3[tid]; }
    if (tid == 0) b3s[0] = b3[0];

    if (tid < TMc) {
        int li = lb * TMc + tid;
        int oi = -1;
        float px = 0.f, py = 0.f, pz = 0.f;
        if (li < pcnt) {
            int ray; float t;
            if (mode == 0) {
                ray = list[li];
                t = tvals[ray];
                oi = ray;
            } else {
                ray = list[li >> 6];
                t = ptsint(g_start[ray], g_end[ray], lint(li & 63));
                oi = li;
            }
            px = __fadd_rn(rayo[ray * 3 + 0], __fmul_rn(t, rayd[ray * 3 + 0]));
            py = __fadd_rn(rayo[ray * 3 + 1], __fmul_rn(t, rayd[ray * 3 + 1]));
            pz = __fadd_rn(rayo[ray * 3 + 2], __fmul_rn(t, rayd[ray * 3 + 2]));
        }
        Ps[tid * 4 + 0] = px; Ps[tid * 4 + 1] = py; Ps[tid * 4 + 2] = pz; Ps[tid * 4 + 3] = 0.f;
        oix[tid] = oi;
    }
    __syncthreads();

    // layer 1 (HsT pitch TMc): HDIM x TMc elements
    for (int idx = tid; idx < HDIM * TMc; idx += 256) {
        int k = idx / TMc, m = idx % TMc;
        float v = __fmaf_rn(Ps[m * 4 + 0], w1s[k], 0.0f);
        v = __fmaf_rn(Ps[m * 4 + 1], w1s[HDIM + k], v);
        v = __fmaf_rn(Ps[m * 4 + 2], w1s[2 * HDIM + k], v);
        v = __fadd_rn(v, b1s[k]);
        HsT[k * TMc + m] = softplus_x(v);
    }
    __syncthreads();

    // layer 2: acc=0, ascending-k fma chains; R x 8 register tile per thread;
    // W2 streamed from global (L1-resident).
    constexpr int R = TMc / 16;
    const int tx = tid & 15, ty = tid >> 4;
    float acc[R][8];
    #pragma unroll
    for (int i = 0; i < R; i++)
        #pragma unroll
        for (int j = 0; j < 8; j++) acc[i][j] = 0.0f;
    const float* hp = HsT + ty * R;
    const float* wp = W2 + tx * 8;
    #pragma unroll 4
    for (int k = 0; k < HDIM; k++) {
        float av[R];
        if constexpr (R == 4) {
            float4 a0 = *(const float4*)(hp + k * TMc);
            av[0] = a0.x; av[1] = a0.y; av[2] = a0.z; av[3] = a0.w;
        } else {
            float2 a0 = *(const float2*)(hp + k * TMc);
            av[0] = a0.x; av[1] = a0.y;
        }
        float4 c0 = __ldg((const float4*)(wp + k * HDIM));
        float4 c1 = __ldg((const float4*)(wp + k * HDIM + 4));
        float bv[8] = {c0.x, c0.y, c0.z, c0.w, c1.x, c1.y, c1.z, c1.w};
        #pragma unroll
        for (int i = 0; i < R; i++)
            #pragma unroll
            for (int j = 0; j < 8; j++)
                acc[i][j] = __fmaf_rn(av[i], bv[j], acc[i][j]);
    }
    __syncthreads();   // all HsT reads done -> safe to overwrite with H3

    #pragma unroll
    for (int i = 0; i < R; i++) {
        int m = ty * R + i;
        #pragma unroll
        for (int j = 0; j < 8; j++) {
            int n = tx * 8 + j;
            float h2 = __fadd_rn(acc[i][j], b2s[n]);
            H3[m * 129 + n] = softplus_x(h2);
        }
    }
    __syncthreads();

    // layer 3: cuBLAS gemv2T-8 order (8 lanes/output), + fused epilogues
    {
        int grp = tid >> 3;
        int l8  = tid & 7;
        #pragma unroll
        for (int rep = 0; rep < TMc / 32; rep++) {
            int m = rep * 32 + grp;
            const float* hrow = H3 + m * 129;
            float p = 0.0f;
            #pragma unroll
            for (int i = 0; i < 16; i++)
                p = __fmaf_rn(hrow[l8 + 8 * i], w3s[l8 + 8 * i], p);
            p = __fadd_rn(p, __shfl_down_sync(0xffffffffu, p, 4, 8));
            p = __fadd_rn(p, __shfl_down_sync(0xffffffffu, p, 2, 8));
            p = __fadd_rn(p, __shfl_down_sync(0xffffffffu, p, 1, 8));
            if (l8 == 0) {
                float corr = __fadd_rn(p, b3s[0]);
                float px = Ps[m * 4 + 0], py = Ps[m * 4 + 1], pz = Ps[m * 4 + 2];
                float s2 = __fadd_rn(__fadd_rn(__fmul_rn(px, px), __fmul_rn(py, py)), __fmul_rn(pz, pz));
                float nr = __fsqrt_rn(s2);
                float sv = __fadd_rn(__fsub_rn(nr, 1.0f), __fmul_rn(0.1f, corr));
                int oi = oix[m];
                if (mode == 1) {
                    svs[m] = sv;
                } else if (oi >= 0) {
                    int ray = oi;
                    if (fuse == 0) {
                        outp[ray] = sv;
                    } else if (fuse == 1) {
                        outp[ray] = sv;
                        if (sv < 0.f) {
                            if (side == 0) {
                                g_start[ray] = __fsub_rn(g_start[ray], __fmul_rn(0.5f, g_curr_s[ray]));
                                int pp = atomicAdd(&g_cnt[xA], 1); g_lc[pp] = ray;
                            } else {
                                g_end[ray] = __fadd_rn(g_end[ray], __fmul_rn(0.5f, g_curr_e[ray]));
                                int pp = atomicAdd(&g_cnt[xB], 1); g_ld[pp] = ray;
                            }
                        }
                    } else {
                        float smv = sv;
                        float zl = g_zlow[ray], zh = g_zhigh[ray], sl = g_slow[ray], sh = g_shigh[ray];
                        float zp = g_zpred[ray];
                        if (smv > 0.f) { zl = zp; sl = smv; }
                        if (smv < 0.f) { zh = zp; sh = smv; }
                        float num = __fmul_rn(-sl, __fsub_rn(zh, zl));
                        float den = __fadd_rn(__fsub_rn(sh, sl), 1e-10f);
                        zp = __fadd_rn(__fdiv_rn(num, den), zl);
                        g_zlow[ray] = zl; g_zhigh[ray] = zh; g_slow[ray] = sl; g_shigh[ray] = sh;
                        g_zpred[ray] = zp;
                    }
                }
            }
        }
    }

    // mode 1 (TMc==64 only): tile = exactly 1 ray; fused argmin + secant init
    if constexpr (TMc == 64) {
        if (mode == 1) {
            __syncthreads();
            int warp = tid >> 5, lane = tid & 31;
            if (warp == 0) {
                int li2 = lb;
                if (li2 < rcnt) {
                    int ray = list[li2];
                    const float* sp = svs;
                    float s0 = sp[lane];
                    float s1 = sp[lane + 32];
                    float sg0 = (s0 > 0.f ? 1.f : (s0 < 0.f ? -1.f : 0.f));
                    float sg1 = (s1 > 0.f ? 1.f : (s1 < 0.f ? -1.f : 0.f));
                    float t0 = sg0 * (float)(64 - lane);
                    float t1 = sg1 * (float)(32 - lane);

                    float bv; int bi;
                    if (t1 < t0) { bv = t1; bi = lane + 32; } else { bv = t0; bi = lane; }
                    float cv; int ci;
                    if (s1 < s0) { cv = s1; ci = lane + 32; } else { cv = s0; ci = lane; }
                    #pragma unroll
                    for (int off = 16; off > 0; off >>= 1) {
                        float ov = __shfl_down_sync(0xffffffffu, bv, off);
                        int   oi2 = __shfl_down_sync(0xffffffffu, bi, off);
                        if (ov < bv || (ov == bv && oi2 < bi)) { bv = ov; bi = oi2; }
                        float pv = __shfl_down_sync(0xffffffffu, cv, off);
                        int   pi = __shfl_down_sync(0xffffffffu, ci, off);
                        if (pv < cv || (pv == cv && pi < ci)) { cv = pv; ci = pi; }
                    }
                    if (lane == 0) {
                        int idx = bi;
                        bool net = (bv < 0.f);
                        int out_idx = ci;
                        bool ob = (obj[ray] != 0);
                        bool p_out = !(ob && net);
                        int sel = p_out ? out_idx : idx;
                        float s = g_start[ray], e = g_end[ray];
                        g_cand[ray]  = ptsint(s, e, lint(sel));
                        g_convf[ray] = net ? 1 : 0;
                        if (net && ob) {
                            g_secf[ray] = 1;
                            int il = (idx + 63) & 63;
                            float zh = ptsint(s, e, lint(idx));
                            float zl = ptsint(s, e, lint(il));
                            float sh = sp[idx];
                            float sl = sp[il];
                            g_zlow[ray] = zl; g_zhigh[ray] = zh; g_slow[ray] = sl; g_shigh[ray] = sh;
                            float num = __fmul_rn(-sl, __fsub_rn(zh, zl));
                            float den = __fadd_rn(__fsub_rn(sh, sl), 1e-10f);
                            g_zpred[ray] = __fadd_rn(__fdiv_rn(num, den), zl);
                            int pp = atomicAdd(&g_cnt[xA], 1); g_ls[pp] = ray;
                        }
                    }
                }
            }
        }
    }
}

// shared sizes per template
static constexpr int smem_for(int TMc) {
    int hh = (HDIM * TMc > TMc * 129) ? HDIM * TMc : TMc * 129;
    int off = hh + 4 * TMc + 3 * HDIM + HDIM + HDIM + HDIM + 4 + TMc + 72;
    return off * 4;
}
#define SMEM32 smem_for(32)   // ~21 KB
#define SMEM64 smem_for(64)   // ~37 KB

// ---------------- control kernels ----------------
__global__ void reset_kernel() {
    if (threadIdx.x < 64) g_cnt[threadIdx.x] = 0;
}

__global__ void init_kernel(const float* __restrict__ fb, const int* __restrict__ mi, int N) {
    int i = blockIdx.x * blockDim.x + threadIdx.x;
    if (i >= N) return;
    g_start[i] = fb[2 * i];
    g_end[i]   = fb[2 * i + 1];
    unsigned char m = mi[i] ? 1 : 0;
    g_uf_s[i] = m; g_uf_e[i] = m;
    g_next_s[i] = 0.f; g_next_e[i] = 0.f;
    g_workf[i] = 0; g_secf[i] = 0; g_convf[i] = 0;
    if (m) { int p = atomicAdd(&g_cnt[0], 1); g_la[p] = i; }
}

__global__ void update1_kernel(int apply_lt, int cs_idx, int ce_idx, int N) {
    int i = blockIdx.x * blockDim.x + threadIdx.x;
    if (i >= N) return;
    unsigned char us = g_uf_s[i], ue = g_uf_e[i];
    float s = g_start[i], e = g_end[i];
    if (apply_lt) { unsigned char lt = (s < e) ? 1 : 0; us &= lt; ue &= lt; }
    float cs = us ? g_next_s[i] : 0.f; if (cs <= THRS) cs = 0.f;
    float ce = ue ? g_next_e[i] : 0.f; if (ce <= THRS) ce = 0.f;
    us = (us && cs > THRS) ? 1 : 0;
    ue = (ue && ce > THRS) ? 1 : 0;
    if (us) s = __fadd_rn(s, cs);
    if (ue) e = __fsub_rn(e, ce);
    g_start[i] = s; g_end[i] = e;
    g_curr_s[i] = cs; g_curr_e[i] = ce;
    g_uf_s[i] = us; g_uf_e[i] = ue;
    if (!us) g_next_s[i] = 0.f;
    if (!ue) g_next_e[i] = 0.f;
    if (us) { int p = atomicAdd(&g_cnt[cs_idx], 1); g_la[p] = i; }
    if (ue) { int p = atomicAdd(&g_cnt[ce_idx], 1); g_lb[p] = i; }
}

__global__ void work_kernel(int c_idx, int N) {
    int i = blockIdx.x * blockDim.x + threadIdx.x;
    if (i >= N) return;
    unsigned char us = g_uf_s[i];
    if (!(g_start[i] < g_end[i])) us = 0;
    unsigned char w = (us && (g_next_s[i] > THRS)) ? 1 : 0;
    g_workf[i] = w;
    if (w) { int p = atomicAdd(&g_cnt[c_idx], 1); g_lw[p] = i; }
}

__global__ void assembly_kernel(const float* __restrict__ rayo, const float* __restrict__ rayd,
                                float* __restrict__ out, int N) {
    int i = blockIdx.x * blockDim.x + threadIdx.x;
    if (i >= N) return;
    float px = 0.f, py = 0.f, pz = 0.f, dist = 0.f;
    if (g_secf[i]) {
        float t = g_zpred[i];
        px = __fadd_rn(rayo[i*3+0], __fmul_rn(t, rayd[i*3+0]));
        py = __fadd_rn(rayo[i*3+1], __fmul_rn(t, rayd[i*3+1]));
        pz = __fadd_rn(rayo[i*3+2], __fmul_rn(t, rayd[i*3+2]));
        dist = t;
    } else if (g_workf[i]) {
        float t = g_cand[i];
        px = __fadd_rn(rayo[i*3+0], __fmul_rn(t, rayd[i*3+0]));
        py = __fadd_rn(rayo[i*3+1], __fmul_rn(t, rayd[i*3+1]));
        pz = __fadd_rn(rayo[i*3+2], __fmul_rn(t, rayd[i*3+2]));
        dist = t;
    }
    out[i*5+0] = px; out[i*5+1] = py; out[i*5+2] = pz;
    out[i*5+3] = dist;
    out[i*5+4] = g_convf[i] ? 1.0f : 0.0f;
}

// ---------------- host orchestration ----------------
extern "C" void kernel_launch(void* const* d_in, const int* in_sizes, int n_in,
                              void* d_out, int out_size)
{
    const float* rayo = (const float*)d_in[0];
    const float* rayd = (const float*)d_in[1];
    const float* fb   = (const float*)d_in[2];
    const float* W1   = (const float*)d_in[3];
    const float* b1   = (const float*)d_in[4];
    const float* W2   = (const float*)d_in[5];
    const float* b2   = (const float*)d_in[6];
    const float* W3   = (const float*)d_in[7];
    const float* b3   = (const float*)d_in[8];
    const int* obj    = (const int*)d_in[9];
    const int* mi     = (const int*)d_in[10];
    int N = in_sizes[0] / 3;
    float* out = (float*)d_out;

    cudaFuncSetAttribute(eval_kernel<32>, cudaFuncAttributeMaxDynamicSharedMemorySize, SMEM32);
    cudaFuncSetAttribute(eval_kernel<64>, cudaFuncAttributeMaxDynamicSharedMemorySize, SMEM64);

    float *p_start, *p_end, *p_ns, *p_ne, *p_zpred;
    int *p_la, *p_lb, *p_lc, *p_ld, *p_lw, *p_ls;
    cudaGetSymbolAddress((void**)&p_start,  g_start);
    cudaGetSymbolAddress((void**)&p_end,    g_end);
    cudaGetSymbolAddress((void**)&p_ns,     g_next_s);
    cudaGetSymbolAddress((void**)&p_ne,     g_next_e);
    cudaGetSymbolAddress((void**)&p_zpred,  g_zpred);
    cudaGetSymbolAddress((void**)&p_la,     g_la);
    cudaGetSymbolAddress((void**)&p_lb,     g_lb);
    cudaGetSymbolAddress((void**)&p_lc,     g_lc);
    cudaGetSymbolAddress((void**)&p_ld,     g_ld);
    cudaGetSymbolAddress((void**)&p_lw,     g_lw);
    cudaGetSymbolAddress((void**)&p_ls,     g_ls);

    const int nb  = (N + 255) / 256;   // 64
    const int eg  = (N + 31) / 32;     // 512 tiles (TM=32)
    const int egd = N;                 // dense tiles: 1 ray each (TM=64)

    reset_kernel<<<1, 64>>>();
    init_kernel<<<nb, 256>>>(fb, mi, N);
    eval_kernel<32><<<2 * eg, 256, SMEM32>>>(0, 0, 0, 0, 0, 0, eg, rayo, rayd, W1, b1, W2, b2, W3, b3,
                                             p_la, p_la, p_start, p_end, p_ns, p_ne, obj);

    for (int it = 0; it < 10; it++) {
        int c1 = 1 + it * 4, c2 = 2 + it * 4, c3 = 3 + it * 4, c4 = 4 + it * 4;
        update1_kernel<<<nb, 256>>>(it > 0 ? 1 : 0, c1, c2, N);
        eval_kernel<32><<<2 * eg, 256, SMEM32>>>(0, 1, c1, c2, c3, c4, eg, rayo, rayd, W1, b1, W2, b2, W3, b3,
                                                 p_la, p_lb, p_start, p_end, p_ns, p_ne, obj);
        eval_kernel<32><<<2 * eg, 256, SMEM32>>>(0, 0, c3, c4, 0, 0, eg, rayo, rayd, W1, b1, W2, b2, W3, b3,
                                                 p_lc, p_ld, p_start, p_end, p_ns, p_ne, obj);
    }

    work_kernel<<<nb, 256>>>(48, N);
    eval_kernel<64><<<egd, 256, SMEM64>>>(1, 0, 48, 48, 49, 49, egd, rayo, rayd, W1, b1, W2, b2, W3, b3,
                                          p_lw, p_lw, p_start, p_start, p_ns, p_ns, obj);

    for (int it = 0; it < 8; it++) {
        eval_kernel<32><<<eg, 256, SMEM32>>>(0, 2, 49, 49, 0, 0, eg, rayo, rayd, W1, b1, W2, b2, W3, b3,
                                             p_ls, p_ls, p_zpred, p_zpred, p_ns, p_ns, obj);
    }

    assembly_kernel<<<nb, 256>>>(rayo, rayd, out, N);
    (void)n_in; (void)out_size; (void)b2;
}

// round 15
// speedup vs baseline: 1.2259x; 1.2259x over previous
#include <cuda_runtime.h>
#include <math.h>

#define MAXN   16384
#define HDIM   128
#define TM     64
#define NSTEPS 64
#define THRS   5e-5f

// ---------------- device state ----------------
__device__ float g_start[MAXN], g_end[MAXN];
__device__ float g_next_s[MAXN], g_next_e[MAXN];
__device__ float g_curr_s[MAXN], g_curr_e[MAXN];
__device__ unsigned char g_uf_s[MAXN], g_uf_e[MAXN];
__device__ unsigned char g_workf[MAXN], g_secf[MAXN], g_convf[MAXN];
__device__ float g_zlow[MAXN], g_zhigh[MAXN], g_slow[MAXN], g_shigh[MAXN];
__device__ float g_zpred[MAXN], g_cand[MAXN];
__device__ int g_cnt[64];
__device__ int g_la[MAXN], g_lb[MAXN], g_lc[MAXN], g_ld[MAXN], g_lw[MAXN], g_ls[MAXN];

// jax.nn.softplus(x) = max(x,0) + log1p(exp(-|x|))  [libdevice expf/log1pf]
__device__ __forceinline__ float softplus_x(float x) {
    return __fadd_rn(fmaxf(x, 0.0f), log1pf(expf(-fabsf(x))));
}
// jnp.linspace(0,1,64)[i]
__device__ __forceinline__ float lint(int i) {
    return (i == 63) ? 1.0f : __fdiv_rn((float)i, 63.0f);
}
// pts_int = start + t*(end-start), uncontracted rn
__device__ __forceinline__ float ptsint(float s, float e, float t) {
    return __fadd_rn(s, __fmul_rn(t, __fsub_rn(e, s)));
}

// ---- packed fp32 FFMA2 (sm_100 f32x2; lane-wise IEEE rn — bit-identical
// to two scalar __fmaf_rn chains) ----
__device__ __forceinline__ unsigned long long pack2same(float v) {
    unsigned long long r;
    asm("mov.b64 %0, {%1, %2};" : "=l"(r) : "f"(v), "f"(v));
    return r;
}
__device__ __forceinline__ unsigned long long fma2(unsigned long long a,
                                                   unsigned long long b,
                                                   unsigned long long c) {
    unsigned long long d;
    asm("fma.rn.f32x2 %0, %1, %2, %3;" : "=l"(d) : "l"(a), "l"(b), "l"(c));
    return d;
}
__device__ __forceinline__ void unpack2(unsigned long long v, float& lo, float& hi) {
    asm("mov.b64 {%0, %1}, %2;" : "=f"(lo), "=f"(hi) : "l"(v));
}

// ---------------- shared layout (floats), TM=64 ----------------
// Union region: HsT (128 x 64, pitch 64 = 8192 floats) during GEMM;
// H3 (64 rows, pitch 129 = 8256 floats) after a sync. Region = 8256.
#define SOFF_HH   0
#define SOFF_PS   8256
#define SOFF_W1   8512
#define SOFF_B1   8896
#define SOFF_B2   9024
#define SOFF_W3   9152
#define SOFF_B3   9280
#define SOFF_OIX  9284
#define SOFF_SV   9348
#define EVAL_SMEM ((9348 + 72) * 4)   // ~36.8 KB -> 4 blocks/SM

// Compacted predicated MLP-SDF eval; per-point math bit-identical to the
// passing r7-r13 kernels (ascending-k fma, bias-after, gemv2T-8 layer 3).
// Layer 2 uses packed f32x2 FFMA (lane-wise rn): same chains, half the instrs.
// fuse: 0=plain write, 1=linestep epilogue, 2=secant-update epilogue.
__global__ void __launch_bounds__(256, 4) eval_kernel(
    int mode, int fuse, int cidxA, int cidxB, int xA, int xB, int gridA,
    const float* __restrict__ rayo, const float* __restrict__ rayd,
    const float* __restrict__ W1, const float* __restrict__ b1,
    const float* __restrict__ W2, const float* __restrict__ b2,
    const float* __restrict__ W3, const float* __restrict__ b3,
    const int* __restrict__ listA, const int* __restrict__ listB,
    const float* __restrict__ tvalsA, const float* __restrict__ tvalsB,
    float* __restrict__ outA, float* __restrict__ outB,
    const int* __restrict__ obj)
{
    extern __shared__ float sbuf[];
    float* HsT = sbuf + SOFF_HH;      // pitch 64 during GEMM
    float* H3  = sbuf + SOFF_HH;      // pitch 129 after GEMM (aliased)
    float* Ps  = sbuf + SOFF_PS;
    float* w1s = sbuf + SOFF_W1;
    float* b1s = sbuf + SOFF_B1;
    float* b2s = sbuf + SOFF_B2;
    float* w3s = sbuf + SOFF_W3;
    float* b3s = sbuf + SOFF_B3;
    float* svs = sbuf + SOFF_SV;
    int*   oix = (int*)(sbuf + SOFF_OIX);

    const int tid = threadIdx.x;
    const int side = (blockIdx.x >= gridA) ? 1 : 0;
    const int lb   = side ? (blockIdx.x - gridA) : blockIdx.x;
    int rcnt = g_cnt[side ? cidxB : cidxA];
    int pcnt = (mode == 1) ? (rcnt << 6) : rcnt;
    if (lb * TM >= pcnt) return;   // idle block

    const int*   list  = side ? listB  : listA;
    const float* tvals = side ? tvalsB : tvalsA;
    float*       outp  = side ? outB   : outA;

    for (int i = tid; i < 3 * HDIM; i += 256) w1s[i] = W1[i];
    if (tid < HDIM) { b1s[tid] = b1[tid]; b2s[tid] = b2[tid]; w3s[tid] = W3[tid]; }
    if (tid == 0) b3s[0] = b3[0];

    if (tid < TM) {
        int li = lb * TM + tid;
        int oi = -1;
        float px = 0.f, py = 0.f, pz = 0.f;
        if (li < pcnt) {
            int ray; float t;
            if (mode == 0) {
                ray = list[li];
                t = tvals[ray];
                oi = ray;
            } else {
                ray = list[li >> 6];
                t = ptsint(g_start[ray], g_end[ray], lint(li & 63));
                oi = li;
            }
            px = __fadd_rn(rayo[ray * 3 + 0], __fmul_rn(t, rayd[ray * 3 + 0]));
            py = __fadd_rn(rayo[ray * 3 + 1], __fmul_rn(t, rayd[ray * 3 + 1]));
            pz = __fadd_rn(rayo[ray * 3 + 2], __fmul_rn(t, rayd[ray * 3 + 2]));
        }
        Ps[tid * 4 + 0] = px; Ps[tid * 4 + 1] = py; Ps[tid * 4 + 2] = pz; Ps[tid * 4 + 3] = 0.f;
        oix[tid] = oi;
    }
    __syncthreads();

    // layer 1 (HsT pitch 64): 128x64 elements
    for (int idx = tid; idx < HDIM * TM; idx += 256) {
        int k = idx >> 6, m = idx & 63;
        float v = __fmaf_rn(Ps[m * 4 + 0], w1s[k], 0.0f);
        v = __fmaf_rn(Ps[m * 4 + 1], w1s[HDIM + k], v);
        v = __fmaf_rn(Ps[m * 4 + 2], w1s[2 * HDIM + k], v);
        v = __fadd_rn(v, b1s[k]);
        HsT[k * TM + m] = softplus_x(v);
    }
    __syncthreads();

    // layer 2: packed f32x2 accumulators over j-pairs; per-(m,n) chain is the
    // same ascending-k fma sequence (lane-wise rn). 4x8 logical tile.
    const int tx = tid & 15, ty = tid >> 4;
    unsigned long long acc2[4][4];
    #pragma unroll
    for (int i = 0; i < 4; i++)
        #pragma unroll
        for (int jp = 0; jp < 4; jp++) acc2[i][jp] = 0ull;   // (+0.0f, +0.0f)
    const float* hp = HsT + ty * 4;
    const float* wp = W2 + tx * 8;
    #pragma unroll 4
    for (int k = 0; k < HDIM; k++) {
        float4 a0 = *(const float4*)(hp + k * TM);
        ulonglong2 w0 = *(const ulonglong2*)(wp + k * HDIM);
        ulonglong2 w1p = *(const ulonglong2*)(wp + k * HDIM + 4);
        unsigned long long bv2[4] = {w0.x, w0.y, w1p.x, w1p.y};
        float av[4] = {a0.x, a0.y, a0.z, a0.w};
        #pragma unroll
        for (int i = 0; i < 4; i++) {
            unsigned long long a2 = pack2same(av[i]);
            #pragma unroll
            for (int jp = 0; jp < 4; jp++)
                acc2[i][jp] = fma2(a2, bv2[jp], acc2[i][jp]);
        }
    }
    __syncthreads();   // all HsT reads done -> safe to overwrite with H3

    #pragma unroll
    for (int i = 0; i < 4; i++) {
        int m = ty * 4 + i;
        #pragma unroll
        for (int jp = 0; jp < 4; jp++) {
            float lo, hi;
            unpack2(acc2[i][jp], lo, hi);
            int n = tx * 8 + jp * 2;
            H3[m * 129 + n]     = softplus_x(__fadd_rn(lo, b2s[n]));
            H3[m * 129 + n + 1] = softplus_x(__fadd_rn(hi, b2s[n + 1]));
        }
    }
    __syncthreads();

    // layer 3: cuBLAS gemv2T-8 order (8 lanes/output), + fused epilogues
    {
        int grp = tid >> 3;
        int l8  = tid & 7;
        #pragma unroll
        for (int rep = 0; rep < 2; rep++) {
            int m = rep * 32 + grp;
            const float* hrow = H3 + m * 129;
            float p = 0.0f;
            #pragma unroll
            for (int i = 0; i < 16; i++)
                p = __fmaf_rn(hrow[l8 + 8 * i], w3s[l8 + 8 * i], p);
            p = __fadd_rn(p, __shfl_down_sync(0xffffffffu, p, 4, 8));
            p = __fadd_rn(p, __shfl_down_sync(0xffffffffu, p, 2, 8));
            p = __fadd_rn(p, __shfl_down_sync(0xffffffffu, p, 1, 8));
            if (l8 == 0) {
                float corr = __fadd_rn(p, b3s[0]);
                float px = Ps[m * 4 + 0], py = Ps[m * 4 + 1], pz = Ps[m * 4 + 2];
                float s2 = __fadd_rn(__fadd_rn(__fmul_rn(px, px), __fmul_rn(py, py)), __fmul_rn(pz, pz));
                float nr = __fsqrt_rn(s2);
                float sv = __fadd_rn(__fsub_rn(nr, 1.0f), __fmul_rn(0.1f, corr));
                int oi = oix[m];
                if (mode == 1) {
                    svs[m] = sv;
                } else if (oi >= 0) {
                    int ray = oi;
                    if (fuse == 0) {
                        outp[ray] = sv;
                    } else if (fuse == 1) {
                        outp[ray] = sv;
                        if (sv < 0.f) {
                            if (side == 0) {
                                g_start[ray] = __fsub_rn(g_start[ray], __fmul_rn(0.5f, g_curr_s[ray]));
                                int pp = atomicAdd(&g_cnt[xA], 1); g_lc[pp] = ray;
                            } else {
                                g_end[ray] = __fadd_rn(g_end[ray], __fmul_rn(0.5f, g_curr_e[ray]));
                                int pp = atomicAdd(&g_cnt[xB], 1); g_ld[pp] = ray;
                            }
                        }
                    } else {
                        float smv = sv;
                        float zl = g_zlow[ray], zh = g_zhigh[ray], sl = g_slow[ray], sh = g_shigh[ray];
                        float zp = g_zpred[ray];
                        if (smv > 0.f) { zl = zp; sl = smv; }
                        if (smv < 0.f) { zh = zp; sh = smv; }
                        float num = __fmul_rn(-sl, __fsub_rn(zh, zl));
                        float den = __fadd_rn(__fsub_rn(sh, sl), 1e-10f);
                        zp = __fadd_rn(__fdiv_rn(num, den), zl);
                        g_zlow[ray] = zl; g_zhigh[ray] = zh; g_slow[ray] = sl; g_shigh[ray] = sh;
                        g_zpred[ray] = zp;
                    }
                }
            }
        }
    }

    // mode 1: tile = exactly 1 ray; fused argmin reduce + secant init
    if (mode == 1) {
        __syncthreads();
        int warp = tid >> 5, lane = tid & 31;
        if (warp == 0) {
            int li2 = lb;
            if (li2 < rcnt) {
                int ray = list[li2];
                const float* sp = svs;
                float s0 = sp[lane];
                float s1 = sp[lane + 32];
                float sg0 = (s0 > 0.f ? 1.f : (s0 < 0.f ? -1.f : 0.f));
                float sg1 = (s1 > 0.f ? 1.f : (s1 < 0.f ? -1.f : 0.f));
                float t0 = sg0 * (float)(64 - lane);
                float t1 = sg1 * (float)(32 - lane);

                float bv; int bi;
                if (t1 < t0) { bv = t1; bi = lane + 32; } else { bv = t0; bi = lane; }
                float cv; int ci;
                if (s1 < s0) { cv = s1; ci = lane + 32; } else { cv = s0; ci = lane; }
                #pragma unroll
                for (int off = 16; off > 0; off >>= 1) {
                    float ov = __shfl_down_sync(0xffffffffu, bv, off);
                    int   oi2 = __shfl_down_sync(0xffffffffu, bi, off);
                    if (ov < bv || (ov == bv && oi2 < bi)) { bv = ov; bi = oi2; }
                    float pv = __shfl_down_sync(0xffffffffu, cv, off);
                    int   pi = __shfl_down_sync(0xffffffffu, ci, off);
                    if (pv < cv || (pv == cv && pi < ci)) { cv = pv; ci = pi; }
                }
                if (lane == 0) {
                    int idx = bi;
                    bool net = (bv < 0.f);
                    int out_idx = ci;
                    bool ob = (obj[ray] != 0);
                    bool p_out = !(ob && net);
                    int sel = p_out ? out_idx : idx;
                    float s = g_start[ray], e = g_end[ray];
                    g_cand[ray]  = ptsint(s, e, lint(sel));
                    g_convf[ray] = net ? 1 : 0;
                    if (net && ob) {
                        g_secf[ray] = 1;
                        int il = (idx + 63) & 63;
                        float zh = ptsint(s, e, lint(idx));
                        float zl = ptsint(s, e, lint(il));
                        float sh = sp[idx];
                        float sl = sp[il];
                        g_zlow[ray] = zl; g_zhigh[ray] = zh; g_slow[ray] = sl; g_shigh[ray] = sh;
                        float num = __fmul_rn(-sl, __fsub_rn(zh, zl));
                        float den = __fadd_rn(__fsub_rn(sh, sl), 1e-10f);
                        g_zpred[ray] = __fadd_rn(__fdiv_rn(num, den), zl);
                        int pp = atomicAdd(&g_cnt[xA], 1); g_ls[pp] = ray;
                    }
                }
            }
        }
    }
}

// ---------------- control kernels ----------------
__global__ void reset_kernel() {
    if (threadIdx.x < 64) g_cnt[threadIdx.x] = 0;
}

__global__ void init_kernel(const float* __restrict__ fb, const int* __restrict__ mi, int N) {
    int i = blockIdx.x * blockDim.x + threadIdx.x;
    if (i >= N) return;
    g_start[i] = fb[2 * i];
    g_end[i]   = fb[2 * i + 1];
    unsigned char m = mi[i] ? 1 : 0;
    g_uf_s[i] = m; g_uf_e[i] = m;
    g_next_s[i] = 0.f; g_next_e[i] = 0.f;
    g_workf[i] = 0; g_secf[i] = 0; g_convf[i] = 0;
    if (m) { int p = atomicAdd(&g_cnt[0], 1); g_la[p] = i; }
}

__global__ void update1_kernel(int apply_lt, int cs_idx, int ce_idx, int N) {
    int i = blockIdx.x * blockDim.x + threadIdx.x;
    if (i >= N) return;
    unsigned char us = g_uf_s[i], ue = g_uf_e[i];
    float s = g_start[i], e = g_end[i];
    if (apply_lt) { unsigned char lt = (s < e) ? 1 : 0; us &= lt; ue &= lt; }
    float cs = us ? g_next_s[i] : 0.f; if (cs <= THRS) cs = 0.f;
    float ce = ue ? g_next_e[i] : 0.f; if (ce <= THRS) ce = 0.f;
    us = (us && cs > THRS) ? 1 : 0;
    ue = (ue && ce > THRS) ? 1 : 0;
    if (us) s = __fadd_rn(s, cs);
    if (ue) e = __fsub_rn(e, ce);
    g_start[i] = s; g_end[i] = e;
    g_curr_s[i] = cs; g_curr_e[i] = ce;
    g_uf_s[i] = us; g_uf_e[i] = ue;
    if (!us) g_next_s[i] = 0.f;
    if (!ue) g_next_e[i] = 0.f;
    if (us) { int p = atomicAdd(&g_cnt[cs_idx], 1); g_la[p] = i; }
    if (ue) { int p = atomicAdd(&g_cnt[ce_idx], 1); g_lb[p] = i; }
}

__global__ void work_kernel(int c_idx, int N) {
    int i = blockIdx.x * blockDim.x + threadIdx.x;
    if (i >= N) return;
    unsigned char us = g_uf_s[i];
    if (!(g_start[i] < g_end[i])) us = 0;
    unsigned char w = (us && (g_next_s[i] > THRS)) ? 1 : 0;
    g_workf[i] = w;
    if (w) { int p = atomicAdd(&g_cnt[c_idx], 1); g_lw[p] = i; }
}

__global__ void assembly_kernel(const float* __restrict__ rayo, const float* __restrict__ rayd,
                                float* __restrict__ out, int N) {
    int i = blockIdx.x * blockDim.x + threadIdx.x;
    if (i >= N) return;
    float px = 0.f, py = 0.f, pz = 0.f, dist = 0.f;
    if (g_secf[i]) {
        float t = g_zpred[i];
        px = __fadd_rn(rayo[i*3+0], __fmul_rn(t, rayd[i*3+0]));
        py = __fadd_rn(rayo[i*3+1], __fmul_rn(t, rayd[i*3+1]));
        pz = __fadd_rn(rayo[i*3+2], __fmul_rn(t, rayd[i*3+2]));
        dist = t;
    } else if (g_workf[i]) {
        float t = g_cand[i];
        px = __fadd_rn(rayo[i*3+0], __fmul_rn(t, rayd[i*3+0]));
        py = __fadd_rn(rayo[i*3+1], __fmul_rn(t, rayd[i*3+1]));
        pz = __fadd_rn(rayo[i*3+2], __fmul_rn(t, rayd[i*3+2]));
        dist = t;
    }
    out[i*5+0] = px; out[i*5+1] = py; out[i*5+2] = pz;
    out[i*5+3] = dist;
    out[i*5+4] = g_convf[i] ? 1.0f : 0.0f;
}

// ---------------- host orchestration ----------------
extern "C" void kernel_launch(void* const* d_in, const int* in_sizes, int n_in,
                              void* d_out, int out_size)
{
    const float* rayo = (const float*)d_in[0];
    const float* rayd = (const float*)d_in[1];
    const float* fb   = (const float*)d_in[2];
    const float* W1   = (const float*)d_in[3];
    const float* b1   = (const float*)d_in[4];
    const float* W2   = (const float*)d_in[5];
    const float* b2   = (const float*)d_in[6];
    const float* W3   = (const float*)d_in[7];
    const float* b3   = (const float*)d_in[8];
    const int* obj    = (const int*)d_in[9];
    const int* mi     = (const int*)d_in[10];
    int N = in_sizes[0] / 3;
    float* out = (float*)d_out;

    cudaFuncSetAttribute(eval_kernel, cudaFuncAttributeMaxDynamicSharedMemorySize, EVAL_SMEM);

    float *p_start, *p_end, *p_ns, *p_ne, *p_zpred;
    int *p_la, *p_lb, *p_lc, *p_ld, *p_lw, *p_ls;
    cudaGetSymbolAddress((void**)&p_start,  g_start);
    cudaGetSymbolAddress((void**)&p_end,    g_end);
    cudaGetSymbolAddress((void**)&p_ns,     g_next_s);
    cudaGetSymbolAddress((void**)&p_ne,     g_next_e);
    cudaGetSymbolAddress((void**)&p_zpred,  g_zpred);
    cudaGetSymbolAddress((void**)&p_la,     g_la);
    cudaGetSymbolAddress((void**)&p_lb,     g_lb);
    cudaGetSymbolAddress((void**)&p_lc,     g_lc);
    cudaGetSymbolAddress((void**)&p_ld,     g_ld);
    cudaGetSymbolAddress((void**)&p_lw,     g_lw);
    cudaGetSymbolAddress((void**)&p_ls,     g_ls);

    const int nb  = (N + 255) / 256;            // 64
    const int eg  = (N + TM - 1) / TM;          // 256
    const int egd = N;                          // dense tiles: 1 ray each (max N)

    reset_kernel<<<1, 64>>>();
    init_kernel<<<nb, 256>>>(fb, mi, N);
    eval_kernel<<<2 * eg, 256, EVAL_SMEM>>>(0, 0, 0, 0, 0, 0, eg, rayo, rayd, W1, b1, W2, b2, W3, b3,
                                            p_la, p_la, p_start, p_end, p_ns, p_ne, obj);

    for (int it = 0; it < 10; it++) {
        int c1 = 1 + it * 4, c2 = 2 + it * 4, c3 = 3 + it * 4, c4 = 4 + it * 4;
        update1_kernel<<<nb, 256>>>(it > 0 ? 1 : 0, c1, c2, N);
        eval_kernel<<<2 * eg, 256, EVAL_SMEM>>>(0, 1, c1, c2, c3, c4, eg, rayo, rayd, W1, b1, W2, b2, W3, b3,
                                                p_la, p_lb, p_start, p_end, p_ns, p_ne, obj);
        eval_kernel<<<2 * eg, 256, EVAL_SMEM>>>(0, 0, c3, c4, 0, 0, eg, rayo, rayd, W1, b1, W2, b2, W3, b3,
                                                p_lc, p_ld, p_start, p_end, p_ns, p_ne, obj);
    }

    work_kernel<<<nb, 256>>>(48, N);
    eval_kernel<<<egd, 256, EVAL_SMEM>>>(1, 0, 48, 48, 49, 49, egd, rayo, rayd, W1, b1, W2, b2, W3, b3,
                                         p_lw, p_lw, p_start, p_start, p_ns, p_ns, obj);

    for (int it = 0; it < 8; it++) {
        eval_kernel<<<eg, 256, EVAL_SMEM>>>(0, 2, 49, 49, 0, 0, eg, rayo, rayd, W1, b1, W2, b2, W3, b3,
                                            p_ls, p_ls, p_zpred, p_zpred, p_ns, p_ns, obj);
    }

    assembly_kernel<<<nb, 256>>>(rayo, rayd, out, N);
    (void)n_in; (void)out_size; (void)b2;
}